// round 15
// baseline (speedup 1.0000x reference)
#include <cuda_runtime.h>
#include <cuda_fp16.h>
#include <math.h>

#define En 512
#define Hn 1024
#define Cn 2048
#define Sn 256
#define Tn 128

#define OFF_PRE   (Tn*En)                 /* 65536  */
#define OFF_ALPHA (OFF_PRE + Tn*Hn)       /* 196608 */
#define OFF_H1F   (OFF_ALPHA + Tn*Sn)     /* 229376 */
#define OFF_H2F   (OFF_H1F + Hn)          /* 230400 */

#define NT 512                             /* threads per block: 126 regs/thread sweet spot */

// ---------------- device scratch (static, no allocation) ----------------
__device__ float g_h1[Hn], g_h2[Hn], g_o1[Hn], g_o2[Hn];
__device__ float g_q[Hn], g_e[Sn], g_ctx[Cn];
__device__ float g_gh1[3*Hn], g_gh2[3*Hn];
__device__ float g_preacc[Hn];
__device__ float g_G1[Tn*3*Hn];      // precomputed W_ih1[:, :512] @ emb_t
__device__ float g_Gpre[Tn*Hn];      // precomputed W_pre[:, :512] @ emb_t
__device__ float g_encT[Cn*Sn];      // encoder_outputs transposed (fp32)
__device__ unsigned g_flags[2048];   // per-block arrival flags (32B stride)
__device__ unsigned g_rel;           // release broadcast word

// fp16 weight copies (converted once per launch in prologue; L2-resident)
__device__ __align__(16) __half hWq   [Hn*Hn];          // 2 MB
__device__ __align__(16) __half hWhh1 [3*Hn*Hn];        // 6 MB
__device__ __align__(16) __half hWhh2 [3*Hn*Hn];        // 6 MB
__device__ __align__(16) __half hWih1c[3*Hn*Cn];        // 12 MB (cols 512..2560)
__device__ __align__(16) __half hWih2 [3*Hn*(Hn+Cn)];   // 18 MB
__device__ __align__(16) __half hWpre [Hn*(Hn+Cn)];     // 6 MB (cols 512..3584)
__device__ __align__(16) __half hWout [En*Hn];          // 1 MB

__global__ void init_kernel(const float* __restrict__ h1, const float* __restrict__ h2) {
    int i = blockIdx.x*blockDim.x + threadIdx.x;
    if (i < 2048) g_flags[i] = 0u;
    if (i == 0) g_rel = 0u;
    if (i < Hn) { g_h1[i] = h1[i]; g_h2[i] = h2[i]; }
}

__device__ __forceinline__ float warpsum(float s) {
#pragma unroll
    for (int o = 16; o; o >>= 1) s += __shfl_xor_sync(0xffffffffu, s, o);
    return s;
}

__device__ __forceinline__ float2 h2f(unsigned u) {
    __half2 h;
    *reinterpret_cast<unsigned*>(&h) = u;
    return __half22float2(h);
}

__device__ __forceinline__ unsigned ld_acq(const unsigned* p) {
    unsigned v;
    asm volatile("ld.global.acquire.gpu.u32 %0, [%1];" : "=r"(v) : "l"(p) : "memory");
    return v;
}
__device__ __forceinline__ void st_rel(unsigned* p, unsigned v) {
    asm volatile("st.global.release.gpu.u32 [%0], %1;" :: "l"(p), "r"(v) : "memory");
}

// single fp16 row dot (row width = NI*256), fp32 accumulate, 4 accumulators
template<int NI>
__device__ __forceinline__ float dotb(const __half* __restrict__ row,
                                      const float* __restrict__ xs, int lane) {
    const uint4*  W = (const uint4*)row;
    const float4* X = (const float4*)xs;
    float s0 = 0.f, s1 = 0.f, s2 = 0.f, s3 = 0.f;
#pragma unroll
    for (int k = 0; k < NI; k++) {
        uint4 w = __ldg(W + k*32 + lane);
        int xi = (k*32 + lane)*2;
        float4 a0 = X[xi], a1 = X[xi+1];
        float2 f;
        f = h2f(w.x); s0 += f.x*a0.x + f.y*a0.y;
        f = h2f(w.y); s1 += f.x*a0.z + f.y*a0.w;
        f = h2f(w.z); s2 += f.x*a1.x + f.y*a1.y;
        f = h2f(w.w); s3 += f.x*a1.z + f.y*a1.w;
    }
    return warpsum((s0 + s1) + (s2 + s3));
}

// 4 contiguous rows (given stride, in halves) x one shared vector, width 1024.
__device__ __forceinline__ void dot4s_1024(const __half* __restrict__ base, size_t stride,
                                           const float* __restrict__ xs, int lane,
                                           float& o0, float& o1, float& o2, float& o3) {
    const uint4* W0 = (const uint4*)(base);
    const uint4* W1 = (const uint4*)(base + stride);
    const uint4* W2 = (const uint4*)(base + 2*stride);
    const uint4* W3 = (const uint4*)(base + 3*stride);
    const float4* X = (const float4*)xs;
    float s0 = 0.f, s1 = 0.f, s2 = 0.f, s3 = 0.f;
#pragma unroll
    for (int k = 0; k < 4; k++) {
        int wi = k*32 + lane, xi = wi*2;
        uint4 w0 = __ldg(W0 + wi);
        uint4 w1 = __ldg(W1 + wi);
        uint4 w2 = __ldg(W2 + wi);
        uint4 w3 = __ldg(W3 + wi);
        float4 a = X[xi], b = X[xi+1];
        float2 f;
        f = h2f(w0.x); s0 += f.x*a.x + f.y*a.y;  f = h2f(w0.y); s0 += f.x*a.z + f.y*a.w;
        f = h2f(w0.z); s0 += f.x*b.x + f.y*b.y;  f = h2f(w0.w); s0 += f.x*b.z + f.y*b.w;
        f = h2f(w1.x); s1 += f.x*a.x + f.y*a.y;  f = h2f(w1.y); s1 += f.x*a.z + f.y*a.w;
        f = h2f(w1.z); s1 += f.x*b.x + f.y*b.y;  f = h2f(w1.w); s1 += f.x*b.z + f.y*b.w;
        f = h2f(w2.x); s2 += f.x*a.x + f.y*a.y;  f = h2f(w2.y); s2 += f.x*a.z + f.y*a.w;
        f = h2f(w2.z); s2 += f.x*b.x + f.y*b.y;  f = h2f(w2.w); s2 += f.x*b.z + f.y*b.w;
        f = h2f(w3.x); s3 += f.x*a.x + f.y*a.y;  f = h2f(w3.y); s3 += f.x*a.z + f.y*a.w;
        f = h2f(w3.z); s3 += f.x*b.x + f.y*b.y;  f = h2f(w3.w); s3 += f.x*b.z + f.y*b.w;
    }
    o0 = warpsum(s0); o1 = warpsum(s1); o2 = warpsum(s2); o3 = warpsum(s3);
}

// 2 arbitrary rows x one shared vector, width NI*256 (fp16)
template<int NI>
__device__ __forceinline__ void dotb2(const __half* __restrict__ r0,
                                      const __half* __restrict__ r1,
                                      const float* __restrict__ xs, int lane,
                                      float& o0, float& o1) {
    const uint4* W0 = (const uint4*)r0;
    const uint4* W1 = (const uint4*)r1;
    const float4* X = (const float4*)xs;
    float s0a = 0.f, s0b = 0.f, s1a = 0.f, s1b = 0.f;
#pragma unroll
    for (int k = 0; k < NI; k++) {
        int wi = k*32 + lane, xi = wi*2;
        uint4 w0 = __ldg(W0 + wi);
        uint4 w1 = __ldg(W1 + wi);
        float4 a = X[xi], b = X[xi+1];
        float2 f;
        f = h2f(w0.x); s0a += f.x*a.x + f.y*a.y;  f = h2f(w0.y); s0b += f.x*a.z + f.y*a.w;
        f = h2f(w0.z); s0a += f.x*b.x + f.y*b.y;  f = h2f(w0.w); s0b += f.x*b.z + f.y*b.w;
        f = h2f(w1.x); s1a += f.x*a.x + f.y*a.y;  f = h2f(w1.y); s1b += f.x*a.z + f.y*a.w;
        f = h2f(w1.z); s1a += f.x*b.x + f.y*b.y;  f = h2f(w1.w); s1b += f.x*b.z + f.y*b.w;
    }
    o0 = warpsum(s0a + s0b); o1 = warpsum(s1a + s1b);
}

// 2 contiguous fp32 rows (width 256) x shared vector (for context GEMV)
__device__ __forceinline__ void rowdot2_256(const float* __restrict__ r0,
                                            const float* __restrict__ r1,
                                            const float* __restrict__ xs, int lane,
                                            float& o0, float& o1) {
    const float4* A = (const float4*)r0;
    const float4* B = (const float4*)r1;
    const float4* X = (const float4*)xs;
    float s0 = 0.f, s1 = 0.f;
#pragma unroll
    for (int k = 0; k < 2; k++) {
        int i = k*32 + lane;
        float4 wa = __ldg(A + i), wb = __ldg(B + i), x = X[i];
        s0 += wa.x*x.x + wa.y*x.y + wa.z*x.z + wa.w*x.w;
        s1 += wb.x*x.x + wb.y*x.y + wb.z*x.z + wb.w*x.w;
    }
    o0 = warpsum(s0); o1 = warpsum(s1);
}

// IVALL-free two-level grid barrier:
//   arrive: per-block release-store to own flag (parallel, no serialization)
//   detect: block 0, one thread per flag, concurrent acquire-polls
//   release: one word, acquire-polled by every block
// Mutable cross-SM data is read via __ldcg (bypasses L1) -> no L1 invalidation needed.
__device__ __forceinline__ void gsync(unsigned &ep, int bid, int nb, int tid) {
    ep++;
    __syncthreads();
    if (tid == 0) st_rel(&g_flags[bid*8], ep);
    if (bid == 0) {
        if (tid < nb) { while (ld_acq(&g_flags[tid*8]) < ep) { } }
        __syncthreads();
        if (tid == 0) st_rel(&g_rel, ep);
    }
    if (tid == 0) { while (ld_acq(&g_rel) < ep) { } }
    __syncthreads();
}

extern "C" __global__ void __launch_bounds__(NT, 1)
decoder_persistent(
    const int*   __restrict__ inputs,
    const float* __restrict__ pk,
    const float* __restrict__ enc,
    const float* __restrict__ embeds,
    const float* __restrict__ Wq,
    const float* __restrict__ v_att,
    const float* __restrict__ W_ih1,
    const float* __restrict__ W_hh1,
    const float* __restrict__ b_ih1,
    const float* __restrict__ b_hh1,
    const float* __restrict__ W_ih2,
    const float* __restrict__ W_hh2,
    const float* __restrict__ b_ih2,
    const float* __restrict__ b_hh2,
    const float* __restrict__ W_pre,
    const float* __restrict__ b_pre,
    const float* __restrict__ W_out,
    const float* __restrict__ b_out,
    float* __restrict__ out)
{
    __shared__ __align__(16) float s_x[8192];     // 32 KB staging
    __shared__ __align__(16) float s_alpha[Sn];
    __shared__ float s_gi[48];
    __shared__ float s_inv;

    const int tid  = threadIdx.x;
    const int lane = tid & 31;
    const int wid  = tid >> 5;                    // 0..15
    const int nb   = gridDim.x;
    const int bid  = blockIdx.x;
    const int nwg  = nb * 16;                     // total warps in grid
    const int gw   = bid*16 + wid;                // global warp id
    const int gth  = bid*NT + tid;
    const int gstr = nb*NT;
    unsigned ep = 0;

    // ======================= PROLOGUE =======================
    // 1) transpose encoder_outputs -> encT[c][s] (fp32)
    for (int idx = gth; idx < Cn*Sn; idx += gstr) {
        int c = idx >> 8, s = idx & 255;
        g_encT[idx] = enc[(size_t)s*Cn + c];
    }
    // 2) fp32 -> fp16 weight conversion
    for (int i = gth; i < Hn*Hn/2; i += gstr)
        ((__half2*)hWq)[i] = __float22half2_rn(((const float2*)Wq)[i]);
    for (int i = gth; i < 3*Hn*Hn/2; i += gstr)
        ((__half2*)hWhh1)[i] = __float22half2_rn(((const float2*)W_hh1)[i]);
    for (int i = gth; i < 3*Hn*Hn/2; i += gstr)
        ((__half2*)hWhh2)[i] = __float22half2_rn(((const float2*)W_hh2)[i]);
    for (int i = gth; i < 3*Hn*(Hn+Cn)/2; i += gstr)
        ((__half2*)hWih2)[i] = __float22half2_rn(((const float2*)W_ih2)[i]);
    for (int i = gth; i < En*Hn/2; i += gstr)
        ((__half2*)hWout)[i] = __float22half2_rn(((const float2*)W_out)[i]);
    for (int i = gth; i < 3*Hn*(Cn/2); i += gstr) {        // W_ih1 cols 512..2560
        int r = i >> 10, c = i & 1023;
        float2 f = *(const float2*)(W_ih1 + (size_t)r*2560 + 512 + 2*c);
        ((__half2*)hWih1c)[i] = __float22half2_rn(f);
    }
    for (int i = gth; i < Hn*((Hn+Cn)/2); i += gstr) {     // W_pre cols 512..3584
        int r = i / 1536, c = i % 1536;
        float2 f = *(const float2*)(W_pre + (size_t)r*3584 + 512 + 2*c);
        ((__half2*)hWpre)[i] = __float22half2_rn(f);
    }
    // 3) emb-part GEMMs (fp32, per-launch): g_G1, g_Gpre
    {
        const int RT = 4*Hn;                       // 4096 rows
        int rb = (RT + nb - 1)/nb;
        int r0 = bid*rb, r1 = min(RT, r0 + rb);
        for (int tile = 0; tile < Tn/16; tile++) {
            __syncthreads();
            for (int idx = tid; idx < 16*En; idx += NT) {
                int tt = idx >> 9, c = idx & 511;
                s_x[idx] = embeds[(size_t)inputs[tile*16 + tt]*En + c];
            }
            __syncthreads();
            for (int rI = r0 + wid; rI < r1; rI += 16) {
                const float* Wrow; float* Gp; int gs;
                if (rI < 3*Hn) { Wrow = W_ih1 + (size_t)rI*2560;          Gp = g_G1  + rI;          gs = 3*Hn; }
                else           { Wrow = W_pre + (size_t)(rI - 3*Hn)*3584; Gp = g_Gpre + (rI - 3*Hn); gs = Hn;  }
                float w[16];
#pragma unroll
                for (int k = 0; k < 16; k++) w[k] = __ldg(Wrow + k*32 + lane);
#pragma unroll
                for (int tt = 0; tt < 16; tt++) {
                    float s = 0.f;
#pragma unroll
                    for (int k = 0; k < 16; k++) s += w[k] * s_x[tt*512 + k*32 + lane];
                    s = warpsum(s);
                    if (lane == 0) Gp[(tile*16 + tt)*gs] = s;
                }
            }
        }
    }
    gsync(ep, bid, nb, tid);

    const int GPB = (Hn + nb - 1)/nb;               // GRU rows owned per block
    const int i0  = bid*GPB;
    const int ng  = max(0, min(GPB, Hn - i0));

    // ======================= MAIN SEQUENTIAL LOOP =======================
    for (int t = 0; t < Tn; t++) {
        // ---- Phase A (quad-macros): q = Wq@h2; (t>0) out[t-1], pre[t-1] ----
        for (int i = tid; i < Hn; i += NT) {
            s_x[i]      = __ldcg(&g_h2[i]);
            s_x[Hn + i] = __ldcg(&g_o2[i]);
        }
        __syncthreads();
        {
            int mt = (t > 0) ? 640 : 256;
            for (int m = gw; m < mt; m += nwg) {
                float o0, o1, o2, o3;
                if (m < 256) {
                    int r = m*4;
                    dot4s_1024(hWq + (size_t)r*Hn, Hn, s_x, lane, o0, o1, o2, o3);
                    if (!lane) { g_q[r] = o0; g_q[r+1] = o1; g_q[r+2] = o2; g_q[r+3] = o3; }
                } else if (m < 384) {
                    int rr = (m-256)*4;
                    dot4s_1024(hWout + (size_t)rr*Hn, Hn, s_x + Hn, lane, o0, o1, o2, o3);
                    if (!lane) {
                        float* d = out + (size_t)(t-1)*En + rr;
                        d[0] = o0 + b_out[rr];   d[1] = o1 + b_out[rr+1];
                        d[2] = o2 + b_out[rr+2]; d[3] = o3 + b_out[rr+3];
                    }
                } else {
                    int rr = (m-384)*4;
                    dot4s_1024(hWpre + (size_t)rr*(Hn+Cn), Hn+Cn, s_x + Hn, lane, o0, o1, o2, o3);
                    if (!lane) {
                        float* d = out + OFF_PRE + (size_t)(t-1)*Hn + rr;
                        float v;
                        v = o0 + __ldcg(&g_preacc[rr])   + b_pre[rr];   d[0] = (v >= 0.f) ? v : 0.01f*v;
                        v = o1 + __ldcg(&g_preacc[rr+1]) + b_pre[rr+1]; d[1] = (v >= 0.f) ? v : 0.01f*v;
                        v = o2 + __ldcg(&g_preacc[rr+2]) + b_pre[rr+2]; d[2] = (v >= 0.f) ? v : 0.01f*v;
                        v = o3 + __ldcg(&g_preacc[rr+3]) + b_pre[rr+3]; d[3] = (v >= 0.f) ? v : 0.01f*v;
                    }
                }
            }
        }
        gsync(ep, bid, nb, tid);

        // ---- Phase B: e (256 singles) + gh1/gh2 (1536 quad-macros) ----
        for (int i = tid; i < Hn; i += NT) {
            s_x[i]        = __ldcg(&g_q[i]);
            s_x[Hn + i]   = __ldcg(&g_h1[i]);
            s_x[2*Hn + i] = __ldcg(&g_h2[i]);
        }
        __syncthreads();
        for (int j = gw; j < 1792; j += nwg) {
            if (j < 256) {
                const float4* p4 = (const float4*)(pk + (size_t)j*Hn);
                const float4* x4 = (const float4*)s_x;
                const float4* v4 = (const float4*)v_att;
                float acc = 0.f;
#pragma unroll 4
                for (int k = lane; k < 256; k += 32) {
                    float4 p = __ldg(p4 + k); float4 q = x4[k]; float4 v = __ldg(v4 + k);
                    acc += tanhf(p.x + q.x)*v.x + tanhf(p.y + q.y)*v.y
                         + tanhf(p.z + q.z)*v.z + tanhf(p.w + q.w)*v.w;
                }
                acc = warpsum(acc);
                if (!lane) g_e[j] = acc;
            } else {
                int m = j - 256;
                float o0, o1, o2, o3;
                if (m < 768) {
                    int rr = m*4;
                    dot4s_1024(hWhh1 + (size_t)rr*Hn, Hn, s_x + Hn, lane, o0, o1, o2, o3);
                    if (!lane) {
                        g_gh1[rr]   = o0 + b_hh1[rr];   g_gh1[rr+1] = o1 + b_hh1[rr+1];
                        g_gh1[rr+2] = o2 + b_hh1[rr+2]; g_gh1[rr+3] = o3 + b_hh1[rr+3];
                    }
                } else {
                    int rr = (m-768)*4;
                    dot4s_1024(hWhh2 + (size_t)rr*Hn, Hn, s_x + 2*Hn, lane, o0, o1, o2, o3);
                    if (!lane) {
                        g_gh2[rr]   = o0 + b_hh2[rr];   g_gh2[rr+1] = o1 + b_hh2[rr+1];
                        g_gh2[rr+2] = o2 + b_hh2[rr+2]; g_gh2[rr+3] = o3 + b_hh2[rr+3];
                    }
                }
            }
        }
        gsync(ep, bid, nb, tid);

        // ---- Phase C: per-block softmax (redundant, cheap) + context (row pairs) ----
        if (wid == 0) {
            float ev[8], m = -1e30f;
#pragma unroll
            for (int k = 0; k < 8; k++) { ev[k] = __ldcg(&g_e[k*32 + lane]); m = fmaxf(m, ev[k]); }
#pragma unroll
            for (int o = 16; o; o >>= 1) m = fmaxf(m, __shfl_xor_sync(0xffffffffu, m, o));
            float sum = 0.f;
#pragma unroll
            for (int k = 0; k < 8; k++) { float a = expf(ev[k] - m); s_alpha[k*32 + lane] = a; sum += a; }
            sum = warpsum(sum);
            if (!lane) s_inv = 1.f/sum;
        }
        __syncthreads();
        {
            float inv = s_inv;
            for (int jp = gw; jp < 1024; jp += nwg) {
                int c = jp*2;
                float o0, o1;
                rowdot2_256(g_encT + (size_t)c*Sn, g_encT + (size_t)(c+1)*Sn, s_alpha, lane, o0, o1);
                if (!lane) { g_ctx[c] = o0 * inv; g_ctx[c+1] = o1 * inv; }
            }
            if (bid == 0)
                for (int s2 = tid; s2 < Sn; s2 += NT)
                    out[OFF_ALPHA + (size_t)t*Sn + s2] = s_alpha[s2] * inv;
        }
        gsync(ep, bid, nb, tid);

        // ---- Phase D: gi1 ctx-part + W_pre ctx-part (job pairs) + GRU1 combine ----
        for (int i = tid; i < Cn; i += NT) s_x[Hn + i] = __ldcg(&g_ctx[i]);
        __syncthreads();
        for (int jp = wid; jp < 2*ng; jp += 16) {
            int itA = 2*jp, itB = 2*jp + 1;
            int gA = itA & 3, iA = i0 + (itA >> 2);
            int gB = itB & 3, iB = i0 + (itB >> 2);
            const __half* rA = (gA < 3) ? hWih1c + (size_t)(gA*Hn + iA)*Cn
                                        : hWpre  + (size_t)iA*(Hn+Cn) + Hn;
            const __half* rB = (gB < 3) ? hWih1c + (size_t)(gB*Hn + iB)*Cn
                                        : hWpre  + (size_t)iB*(Hn+Cn) + Hn;
            float oA, oB;
            dotb2<8>(rA, rB, s_x + Hn, lane, oA, oB);
            if (!lane) {
                if (gA < 3) s_gi[gA*16 + (itA>>2)] = oA;
                else        g_preacc[iA] = oA + g_Gpre[(size_t)t*Hn + iA];
                if (gB < 3) s_gi[gB*16 + (itB>>2)] = oB;
                else        g_preacc[iB] = oB + g_Gpre[(size_t)t*Hn + iB];
            }
        }
        __syncthreads();
        if (tid < ng) {
            int i = i0 + tid;
            const float* G = g_G1 + (size_t)t*3*Hn;
            float gir = G[i]        + s_gi[tid]      + b_ih1[i]        + __ldcg(&g_gh1[i]);
            float giz = G[Hn + i]   + s_gi[16 + tid] + b_ih1[Hn + i]   + __ldcg(&g_gh1[Hn + i]);
            float gin = G[2*Hn + i] + s_gi[32 + tid] + b_ih1[2*Hn + i];
            float rg = 1.f/(1.f + expf(-gir));
            float zg = 1.f/(1.f + expf(-giz));
            float nn = tanhf(gin + rg * __ldcg(&g_gh1[2*Hn + i]));
            float hn = (1.f - zg)*nn + zg*__ldcg(&g_h1[i]);
            g_h1[i] = hn;
            g_o1[i] = (hn >= 0.f) ? hn : 0.01f*hn;
        }
        gsync(ep, bid, nb, tid);

        // ---- Phase E: gi2 = Wih2 @ [o1; ctx] (job pairs) + GRU2 combine ----
        for (int i = tid; i < Hn; i += NT) s_x[i] = __ldcg(&g_o1[i]);   // ctx persists at s_x[1024..3072)
        __syncthreads();
        {
            int npair = (3*ng + 1) >> 1;
            for (int jp = wid; jp < npair; jp += 16) {
                int itA = 2*jp, itB = 2*jp + 1;
                int vB = (itB < 3*ng);
                int gA = itA % 3, iA = itA / 3;
                int gB = vB ? (itB % 3) : gA, iB = vB ? (itB / 3) : iA;
                const __half* rA = hWih2 + (size_t)(gA*Hn + i0 + iA)*(Hn+Cn);
                const __half* rB = hWih2 + (size_t)(gB*Hn + i0 + iB)*(Hn+Cn);
                float oA, oB;
                dotb2<12>(rA, rB, s_x, lane, oA, oB);
                if (!lane) {
                    s_gi[gA*16 + iA] = oA;
                    if (vB) s_gi[gB*16 + iB] = oB;
                }
            }
        }
        __syncthreads();
        if (tid < ng) {
            int i = i0 + tid;
            float gir = s_gi[tid]      + b_ih2[i]        + __ldcg(&g_gh2[i]);
            float giz = s_gi[16 + tid] + b_ih2[Hn + i]   + __ldcg(&g_gh2[Hn + i]);
            float gin = s_gi[32 + tid] + b_ih2[2*Hn + i];
            float rg = 1.f/(1.f + expf(-gir));
            float zg = 1.f/(1.f + expf(-giz));
            float nn = tanhf(gin + rg * __ldcg(&g_gh2[2*Hn + i]));
            float hn = (1.f - zg)*nn + zg*__ldcg(&g_h2[i]);
            g_h2[i] = hn;
            g_o2[i] = (hn >= 0.f) ? hn : 0.01f*hn;
        }
        gsync(ep, bid, nb, tid);
    }

    // ======================= EPILOGUE: out[127], pre[127], h1f, h2f =======================
    for (int i = tid; i < Hn; i += NT) s_x[i] = __ldcg(&g_o2[i]);
    __syncthreads();
    for (int r = gw; r < 1536; r += nwg) {
        if (r < 512) {
            float s = dotb<4>(hWout + (size_t)r*Hn, s_x, lane);
            if (!lane) out[(size_t)127*En + r] = s + b_out[r];
        } else {
            int rr = r - 512;
            float s = dotb<4>(hWpre + (size_t)rr*(Hn+Cn), s_x, lane);
            if (!lane) {
                float v = s + __ldcg(&g_preacc[rr]) + b_pre[rr];
                out[OFF_PRE + (size_t)127*Hn + rr] = (v >= 0.f) ? v : 0.01f*v;
            }
        }
    }
    for (int i = gth; i < Hn; i += gstr) {
        out[OFF_H1F + i] = __ldcg(&g_h1[i]);
        out[OFF_H2F + i] = __ldcg(&g_h2[i]);
    }
}

extern "C" void kernel_launch(void* const* d_in, const int* in_sizes, int n_in,
                              void* d_out, int out_size) {
    (void)in_sizes; (void)n_in; (void)out_size;
    const int*   inputs = (const int*)  d_in[0];
    const float* h1     = (const float*)d_in[1];
    const float* h2     = (const float*)d_in[2];
    const float* pk     = (const float*)d_in[3];
    const float* enc    = (const float*)d_in[4];
    const float* embeds = (const float*)d_in[5];
    const float* Wq     = (const float*)d_in[6];
    const float* v_att  = (const float*)d_in[7];
    const float* W_ih1  = (const float*)d_in[8];
    const float* W_hh1  = (const float*)d_in[9];
    const float* b_ih1  = (const float*)d_in[10];
    const float* b_hh1  = (const float*)d_in[11];
    const float* W_ih2  = (const float*)d_in[12];
    const float* W_hh2  = (const float*)d_in[13];
    const float* b_ih2  = (const float*)d_in[14];
    const float* b_hh2  = (const float*)d_in[15];
    const float* W_pre  = (const float*)d_in[16];
    const float* b_pre  = (const float*)d_in[17];
    const float* W_out  = (const float*)d_in[18];
    const float* b_out  = (const float*)d_in[19];
    float* out = (float*)d_out;

    int dev = 0, nsm = 148;
    cudaGetDevice(&dev);
    cudaDeviceGetAttribute(&nsm, cudaDevAttrMultiProcessorCount, dev);

    init_kernel<<<2, 1024>>>(h1, h2);
    decoder_persistent<<<nsm, NT>>>(inputs, pk, enc, embeds, Wq, v_att,
                                    W_ih1, W_hh1, b_ih1, b_hh1,
                                    W_ih2, W_hh2, b_ih2, b_hh2,
                                    W_pre, b_pre, W_out, b_out, out);
}

// round 17
// speedup vs baseline: 1.3348x; 1.3348x over previous
#include <cuda_runtime.h>
#include <cuda_fp16.h>
#include <math.h>

#define En 512
#define Hn 1024
#define Cn 2048
#define Sn 256
#define Tn 128

#define OFF_PRE   (Tn*En)                 /* 65536  */
#define OFF_ALPHA (OFF_PRE + Tn*Hn)       /* 196608 */
#define OFF_H1F   (OFF_ALPHA + Tn*Sn)     /* 229376 */
#define OFF_H2F   (OFF_H1F + Hn)          /* 230400 */

#define NT 512                             /* threads per block: 126 regs/thread sweet spot */

// ---------------- device scratch (static, no allocation) ----------------
__device__ float g_h1[Hn], g_h2[Hn], g_o1[Hn], g_o2[Hn];
__device__ float g_q2[2][Hn];        // double-buffered q (accumulated in phase E)
__device__ float g_e[Sn], g_ctx[Cn];
__device__ float g_gh1[3*Hn], g_gh2[3*Hn];
__device__ float g_preacc[Hn];
__device__ float g_G1[Tn*3*Hn];      // precomputed W_ih1[:, :512] @ emb_t
__device__ float g_Gpre[Tn*Hn];      // precomputed W_pre[:, :512] @ emb_t
__device__ float g_encT[Cn*Sn];      // encoder_outputs transposed (fp32)
__device__ unsigned g_bar;

// fp16 weight copies (converted once per launch in prologue; L2-resident)
__device__ __align__(16) __half hWqT  [Hn*Hn];          // 2 MB, TRANSPOSED [c][r]
__device__ __align__(16) __half hWhh1 [3*Hn*Hn];        // 6 MB
__device__ __align__(16) __half hWhh2 [3*Hn*Hn];        // 6 MB
__device__ __align__(16) __half hWih1c[3*Hn*Cn];        // 12 MB (cols 512..2560)
__device__ __align__(16) __half hWih2 [3*Hn*(Hn+Cn)];   // 18 MB
__device__ __align__(16) __half hWpre [Hn*(Hn+Cn)];     // 6 MB (cols 512..3584)
__device__ __align__(16) __half hWout [En*Hn];          // 1 MB

__global__ void init_kernel(const float* __restrict__ h1, const float* __restrict__ h2) {
    int i = blockIdx.x*blockDim.x + threadIdx.x;
    if (i == 0) g_bar = 0u;
    if (i < Hn) { g_h1[i] = h1[i]; g_h2[i] = h2[i]; }
}

__device__ __forceinline__ float warpsum(float s) {
#pragma unroll
    for (int o = 16; o; o >>= 1) s += __shfl_xor_sync(0xffffffffu, s, o);
    return s;
}

__device__ __forceinline__ float2 h2f(unsigned u) {
    __half2 h;
    *reinterpret_cast<unsigned*>(&h) = u;
    return __half22float2(h);
}

// warp-cooperative fp32 row dot (global row x shared vec)
__device__ __forceinline__ float rowdot(const float* __restrict__ Wrow,
                                        const float* __restrict__ xs,
                                        int n4, int lane) {
    const float4* __restrict__ W4 = (const float4*)Wrow;
    const float4* __restrict__ X4 = (const float4*)xs;
    float s = 0.f;
#pragma unroll 8
    for (int k = lane; k < n4; k += 32) {
        float4 w = __ldg(W4 + k);
        float4 x = X4[k];
        s += w.x*x.x + w.y*x.y + w.z*x.z + w.w*x.w;
    }
    return warpsum(s);
}

// single fp16 row dot (row width = NI*256), fp32 accumulate, 4 accumulators
template<int NI>
__device__ __forceinline__ float dotb(const __half* __restrict__ row,
                                      const float* __restrict__ xs, int lane) {
    const uint4*  W = (const uint4*)row;
    const float4* X = (const float4*)xs;
    float s0 = 0.f, s1 = 0.f, s2 = 0.f, s3 = 0.f;
#pragma unroll
    for (int k = 0; k < NI; k++) {
        uint4 w = __ldg(W + k*32 + lane);
        int xi = (k*32 + lane)*2;
        float4 a0 = X[xi], a1 = X[xi+1];
        float2 f;
        f = h2f(w.x); s0 += f.x*a0.x + f.y*a0.y;
        f = h2f(w.y); s1 += f.x*a0.z + f.y*a0.w;
        f = h2f(w.z); s2 += f.x*a1.x + f.y*a1.y;
        f = h2f(w.w); s3 += f.x*a1.z + f.y*a1.w;
    }
    return warpsum((s0 + s1) + (s2 + s3));
}

// 4 contiguous rows (given stride, in halves) x one shared vector, width 1024.
__device__ __forceinline__ void dot4s_1024(const __half* __restrict__ base, size_t stride,
                                           const float* __restrict__ xs, int lane,
                                           float& o0, float& o1, float& o2, float& o3) {
    const uint4* W0 = (const uint4*)(base);
    const uint4* W1 = (const uint4*)(base + stride);
    const uint4* W2 = (const uint4*)(base + 2*stride);
    const uint4* W3 = (const uint4*)(base + 3*stride);
    const float4* X = (const float4*)xs;
    float s0 = 0.f, s1 = 0.f, s2 = 0.f, s3 = 0.f;
#pragma unroll
    for (int k = 0; k < 4; k++) {
        int wi = k*32 + lane, xi = wi*2;
        uint4 w0 = __ldg(W0 + wi);
        uint4 w1 = __ldg(W1 + wi);
        uint4 w2 = __ldg(W2 + wi);
        uint4 w3 = __ldg(W3 + wi);
        float4 a = X[xi], b = X[xi+1];
        float2 f;
        f = h2f(w0.x); s0 += f.x*a.x + f.y*a.y;  f = h2f(w0.y); s0 += f.x*a.z + f.y*a.w;
        f = h2f(w0.z); s0 += f.x*b.x + f.y*b.y;  f = h2f(w0.w); s0 += f.x*b.z + f.y*b.w;
        f = h2f(w1.x); s1 += f.x*a.x + f.y*a.y;  f = h2f(w1.y); s1 += f.x*a.z + f.y*a.w;
        f = h2f(w1.z); s1 += f.x*b.x + f.y*b.y;  f = h2f(w1.w); s1 += f.x*b.z + f.y*b.w;
        f = h2f(w2.x); s2 += f.x*a.x + f.y*a.y;  f = h2f(w2.y); s2 += f.x*a.z + f.y*a.w;
        f = h2f(w2.z); s2 += f.x*b.x + f.y*b.y;  f = h2f(w2.w); s2 += f.x*b.z + f.y*b.w;
        f = h2f(w3.x); s3 += f.x*a.x + f.y*a.y;  f = h2f(w3.y); s3 += f.x*a.z + f.y*a.w;
        f = h2f(w3.z); s3 += f.x*b.x + f.y*b.y;  f = h2f(w3.w); s3 += f.x*b.z + f.y*b.w;
    }
    o0 = warpsum(s0); o1 = warpsum(s1); o2 = warpsum(s2); o3 = warpsum(s3);
}

// 2 arbitrary rows x one shared vector, width NI*256 (fp16)
template<int NI>
__device__ __forceinline__ void dotb2(const __half* __restrict__ r0,
                                      const __half* __restrict__ r1,
                                      const float* __restrict__ xs, int lane,
                                      float& o0, float& o1) {
    const uint4* W0 = (const uint4*)r0;
    const uint4* W1 = (const uint4*)r1;
    const float4* X = (const float4*)xs;
    float s0a = 0.f, s0b = 0.f, s1a = 0.f, s1b = 0.f;
#pragma unroll
    for (int k = 0; k < NI; k++) {
        int wi = k*32 + lane, xi = wi*2;
        uint4 w0 = __ldg(W0 + wi);
        uint4 w1 = __ldg(W1 + wi);
        float4 a = X[xi], b = X[xi+1];
        float2 f;
        f = h2f(w0.x); s0a += f.x*a.x + f.y*a.y;  f = h2f(w0.y); s0b += f.x*a.z + f.y*a.w;
        f = h2f(w0.z); s0a += f.x*b.x + f.y*b.y;  f = h2f(w0.w); s0b += f.x*b.z + f.y*b.w;
        f = h2f(w1.x); s1a += f.x*a.x + f.y*a.y;  f = h2f(w1.y); s1b += f.x*a.z + f.y*a.w;
        f = h2f(w1.z); s1a += f.x*b.x + f.y*b.y;  f = h2f(w1.w); s1b += f.x*b.z + f.y*b.w;
    }
    o0 = warpsum(s0a + s0b); o1 = warpsum(s1a + s1b);
}

// 2 contiguous fp32 rows (width 256) x shared vector (for context GEMV)
__device__ __forceinline__ void rowdot2_256(const float* __restrict__ r0,
                                            const float* __restrict__ r1,
                                            const float* __restrict__ xs, int lane,
                                            float& o0, float& o1) {
    const float4* A = (const float4*)r0;
    const float4* B = (const float4*)r1;
    const float4* X = (const float4*)xs;
    float s0 = 0.f, s1 = 0.f;
#pragma unroll
    for (int k = 0; k < 2; k++) {
        int i = k*32 + lane;
        float4 wa = __ldg(A + i), wb = __ldg(B + i), x = X[i];
        s0 += wa.x*x.x + wa.y*x.y + wa.z*x.z + wa.w*x.w;
        s1 += wb.x*x.x + wb.y*x.y + wb.z*x.z + wb.w*x.w;
    }
    o0 = warpsum(s0); o1 = warpsum(s1);
}

// grid barrier (R14-proven fastest): atomic counter + gpu-scope fences
__device__ __forceinline__ void gsync(unsigned &ep) {
    ep++;
    __syncthreads();
    if (threadIdx.x == 0) {
        __threadfence();                  // release (CCTL.IVALL)
        atomicAdd(&g_bar, 1u);
        unsigned target = ep * gridDim.x;
        volatile unsigned* p = &g_bar;
        while (*p < target) { }
        __threadfence();                  // acquire
    }
    __syncthreads();
}

extern "C" __global__ void __launch_bounds__(NT, 1)
decoder_persistent(
    const int*   __restrict__ inputs,
    const float* __restrict__ pk,
    const float* __restrict__ enc,
    const float* __restrict__ embeds,
    const float* __restrict__ Wq,
    const float* __restrict__ v_att,
    const float* __restrict__ W_ih1,
    const float* __restrict__ W_hh1,
    const float* __restrict__ b_ih1,
    const float* __restrict__ b_hh1,
    const float* __restrict__ W_ih2,
    const float* __restrict__ W_hh2,
    const float* __restrict__ b_ih2,
    const float* __restrict__ b_hh2,
    const float* __restrict__ W_pre,
    const float* __restrict__ b_pre,
    const float* __restrict__ W_out,
    const float* __restrict__ b_out,
    float* __restrict__ out)
{
    __shared__ __align__(16) float s_x[8192];     // 32 KB staging
    __shared__ __align__(16) float s_alpha[Sn];
    __shared__ float s_gi[48];
    __shared__ float s_h2n[8];
    __shared__ float s_inv;

    const int tid  = threadIdx.x;
    const int lane = tid & 31;
    const int wid  = tid >> 5;                    // 0..15
    const int nb   = gridDim.x;
    const int bid  = blockIdx.x;
    const int nwg  = nb * 16;                     // total warps in grid
    const int gw   = bid*16 + wid;                // global warp id
    const int gth  = bid*NT + tid;
    const int gstr = nb*NT;
    unsigned ep = 0;

    // ======================= PROLOGUE =======================
    // 1) transpose encoder_outputs -> encT[c][s] (fp32)
    for (int idx = gth; idx < Cn*Sn; idx += gstr) {
        int c = idx >> 8, s = idx & 255;
        g_encT[idx] = enc[(size_t)s*Cn + c];
    }
    // 2) fp32 -> fp16 weight conversion (+ Wq transpose)
    for (int i = gth; i < Hn*Hn; i += gstr) {              // WqT[c][r] = Wq[r][c]
        int r = i >> 10, c = i & 1023;
        hWqT[(size_t)c*Hn + r] = __float2half(Wq[i]);
    }
    for (int i = gth; i < 3*Hn*Hn/2; i += gstr)
        ((__half2*)hWhh1)[i] = __float22half2_rn(((const float2*)W_hh1)[i]);
    for (int i = gth; i < 3*Hn*Hn/2; i += gstr)
        ((__half2*)hWhh2)[i] = __float22half2_rn(((const float2*)W_hh2)[i]);
    for (int i = gth; i < 3*Hn*(Hn+Cn)/2; i += gstr)
        ((__half2*)hWih2)[i] = __float22half2_rn(((const float2*)W_ih2)[i]);
    for (int i = gth; i < En*Hn/2; i += gstr)
        ((__half2*)hWout)[i] = __float22half2_rn(((const float2*)W_out)[i]);
    for (int i = gth; i < 3*Hn*(Cn/2); i += gstr) {        // W_ih1 cols 512..2560
        int r = i >> 10, c = i & 1023;
        float2 f = *(const float2*)(W_ih1 + (size_t)r*2560 + 512 + 2*c);
        ((__half2*)hWih1c)[i] = __float22half2_rn(f);
    }
    for (int i = gth; i < Hn*((Hn+Cn)/2); i += gstr) {     // W_pre cols 512..3584
        int r = i / 1536, c = i % 1536;
        float2 f = *(const float2*)(W_pre + (size_t)r*3584 + 512 + 2*c);
        ((__half2*)hWpre)[i] = __float22half2_rn(f);
    }
    // 3) emb-part GEMMs (fp32, per-launch): g_G1, g_Gpre
    {
        const int RT = 4*Hn;                       // 4096 rows
        int rb = (RT + nb - 1)/nb;
        int r0 = bid*rb, r1 = min(RT, r0 + rb);
        for (int tile = 0; tile < Tn/16; tile++) {
            __syncthreads();
            for (int idx = tid; idx < 16*En; idx += NT) {
                int tt = idx >> 9, c = idx & 511;
                s_x[idx] = embeds[(size_t)inputs[tile*16 + tt]*En + c];
            }
            __syncthreads();
            for (int rI = r0 + wid; rI < r1; rI += 16) {
                const float* Wrow; float* Gp; int gs;
                if (rI < 3*Hn) { Wrow = W_ih1 + (size_t)rI*2560;          Gp = g_G1  + rI;          gs = 3*Hn; }
                else           { Wrow = W_pre + (size_t)(rI - 3*Hn)*3584; Gp = g_Gpre + (rI - 3*Hn); gs = Hn;  }
                float w[16];
#pragma unroll
                for (int k = 0; k < 16; k++) w[k] = __ldg(Wrow + k*32 + lane);
#pragma unroll
                for (int tt = 0; tt < 16; tt++) {
                    float s = 0.f;
#pragma unroll
                    for (int k = 0; k < 16; k++) s += w[k] * s_x[tt*512 + k*32 + lane];
                    s = warpsum(s);
                    if (lane == 0) Gp[(tile*16 + tt)*gs] = s;
                }
            }
        }
    }
    // 4) initial q = Wq @ h2_init (fp32), and zero q buffer 1
    __syncthreads();
    for (int i = tid; i < Hn; i += NT) s_x[i] = g_h2[i];
    __syncthreads();
    if (gw < Hn) {
        float s = rowdot(Wq + (size_t)gw*Hn, s_x, 256, lane);
        if (!lane) g_q2[0][gw] = s;
    }
    if (bid == 1)
        for (int i = tid; i < Hn; i += NT) g_q2[1][i] = 0.f;
    gsync(ep);

    const int GPB = (Hn + nb - 1)/nb;               // GRU rows owned per block
    const int i0  = bid*GPB;
    const int ng  = max(0, min(GPB, Hn - i0));

    // ======================= MAIN SEQUENTIAL LOOP (4 phases/step) =======================
    for (int t = 0; t < Tn; t++) {
        // ---- Phase B: e(q) + gh1 + gh2 + (t>0) out[t-1], pre[t-1]  (2176 jobs) ----
        {
            const float* qcur = g_q2[t & 1];
            for (int i = tid; i < Hn; i += NT) {
                s_x[i]        = qcur[i];
                s_x[Hn + i]   = g_h1[i];
                s_x[2*Hn + i] = g_h2[i];
                s_x[3*Hn + i] = g_o2[i];
            }
        }
        __syncthreads();
        {
            int tot = (t > 0) ? 2176 : 1792;
            for (int j = gw; j < tot; j += nwg) {
                if (j < 256) {
                    const float4* p4 = (const float4*)(pk + (size_t)j*Hn);
                    const float4* x4 = (const float4*)s_x;
                    const float4* v4 = (const float4*)v_att;
                    float acc = 0.f;
#pragma unroll 4
                    for (int k = lane; k < 256; k += 32) {
                        float4 p = __ldg(p4 + k); float4 q = x4[k]; float4 v = __ldg(v4 + k);
                        acc += tanhf(p.x + q.x)*v.x + tanhf(p.y + q.y)*v.y
                             + tanhf(p.z + q.z)*v.z + tanhf(p.w + q.w)*v.w;
                    }
                    acc = warpsum(acc);
                    if (!lane) g_e[j] = acc;
                } else if (j < 1024) {
                    int rr = (j-256)*4;
                    float o0, o1, o2, o3;
                    dot4s_1024(hWhh1 + (size_t)rr*Hn, Hn, s_x + Hn, lane, o0, o1, o2, o3);
                    if (!lane) {
                        g_gh1[rr]   = o0 + b_hh1[rr];   g_gh1[rr+1] = o1 + b_hh1[rr+1];
                        g_gh1[rr+2] = o2 + b_hh1[rr+2]; g_gh1[rr+3] = o3 + b_hh1[rr+3];
                    }
                } else if (j < 1792) {
                    int rr = (j-1024)*4;
                    float o0, o1, o2, o3;
                    dot4s_1024(hWhh2 + (size_t)rr*Hn, Hn, s_x + 2*Hn, lane, o0, o1, o2, o3);
                    if (!lane) {
                        g_gh2[rr]   = o0 + b_hh2[rr];   g_gh2[rr+1] = o1 + b_hh2[rr+1];
                        g_gh2[rr+2] = o2 + b_hh2[rr+2]; g_gh2[rr+3] = o3 + b_hh2[rr+3];
                    }
                } else if (j < 1920) {
                    int rr = (j-1792)*4;
                    float o0, o1, o2, o3;
                    dot4s_1024(hWout + (size_t)rr*Hn, Hn, s_x + 3*Hn, lane, o0, o1, o2, o3);
                    if (!lane) {
                        float* d = out + (size_t)(t-1)*En + rr;
                        d[0] = o0 + b_out[rr];   d[1] = o1 + b_out[rr+1];
                        d[2] = o2 + b_out[rr+2]; d[3] = o3 + b_out[rr+3];
                    }
                } else {
                    int rr = (j-1920)*4;
                    float o0, o1, o2, o3;
                    dot4s_1024(hWpre + (size_t)rr*(Hn+Cn), Hn+Cn, s_x + 3*Hn, lane, o0, o1, o2, o3);
                    if (!lane) {
                        float* d = out + OFF_PRE + (size_t)(t-1)*Hn + rr;
                        float v;
                        v = o0 + g_preacc[rr]   + b_pre[rr];   d[0] = (v >= 0.f) ? v : 0.01f*v;
                        v = o1 + g_preacc[rr+1] + b_pre[rr+1]; d[1] = (v >= 0.f) ? v : 0.01f*v;
                        v = o2 + g_preacc[rr+2] + b_pre[rr+2]; d[2] = (v >= 0.f) ? v : 0.01f*v;
                        v = o3 + g_preacc[rr+3] + b_pre[rr+3]; d[3] = (v >= 0.f) ? v : 0.01f*v;
                    }
                }
            }
        }
        gsync(ep);

        // ---- Phase C: per-block softmax + context (row pairs) + zero next q buffer ----
        if (wid == 0) {
            float ev[8], m = -1e30f;
#pragma unroll
            for (int k = 0; k < 8; k++) { ev[k] = g_e[k*32 + lane]; m = fmaxf(m, ev[k]); }
#pragma unroll
            for (int o = 16; o; o >>= 1) m = fmaxf(m, __shfl_xor_sync(0xffffffffu, m, o));
            float sum = 0.f;
#pragma unroll
            for (int k = 0; k < 8; k++) { float a = expf(ev[k] - m); s_alpha[k*32 + lane] = a; sum += a; }
            sum = warpsum(sum);
            if (!lane) s_inv = 1.f/sum;
        }
        __syncthreads();
        {
            float inv = s_inv;
            for (int jp = gw; jp < 1024; jp += nwg) {
                int c = jp*2;
                float o0, o1;
                rowdot2_256(g_encT + (size_t)c*Sn, g_encT + (size_t)(c+1)*Sn, s_alpha, lane, o0, o1);
                if (!lane) { g_ctx[c] = o0 * inv; g_ctx[c+1] = o1 * inv; }
            }
            if (bid == 0)
                for (int s2 = tid; s2 < Sn; s2 += NT)
                    out[OFF_ALPHA + (size_t)t*Sn + s2] = s_alpha[s2] * inv;
            if (bid == 1) {
                float* qn = g_q2[(t+1) & 1];
                for (int i = tid; i < Hn; i += NT) qn[i] = 0.f;
            }
        }
        gsync(ep);

        // ---- Phase D: gi1 ctx-part + W_pre ctx-part (job pairs) + GRU1 combine ----
        for (int i = tid; i < Cn; i += NT) s_x[Hn + i] = g_ctx[i];
        __syncthreads();
        for (int jp = wid; jp < 2*ng; jp += 16) {
            int itA = 2*jp, itB = 2*jp + 1;
            int gA = itA & 3, iA = i0 + (itA >> 2);
            int gB = itB & 3, iB = i0 + (itB >> 2);
            const __half* rA = (gA < 3) ? hWih1c + (size_t)(gA*Hn + iA)*Cn
                                        : hWpre  + (size_t)iA*(Hn+Cn) + Hn;
            const __half* rB = (gB < 3) ? hWih1c + (size_t)(gB*Hn + iB)*Cn
                                        : hWpre  + (size_t)iB*(Hn+Cn) + Hn;
            float oA, oB;
            dotb2<8>(rA, rB, s_x + Hn, lane, oA, oB);
            if (!lane) {
                if (gA < 3) s_gi[gA*16 + (itA>>2)] = oA;
                else        g_preacc[iA] = oA + g_Gpre[(size_t)t*Hn + iA];
                if (gB < 3) s_gi[gB*16 + (itB>>2)] = oB;
                else        g_preacc[iB] = oB + g_Gpre[(size_t)t*Hn + iB];
            }
        }
        __syncthreads();
        if (tid < ng) {
            int i = i0 + tid;
            const float* G = g_G1 + (size_t)t*3*Hn;
            float gir = G[i]        + s_gi[tid]      + b_ih1[i]        + g_gh1[i];
            float giz = G[Hn + i]   + s_gi[16 + tid] + b_ih1[Hn + i]   + g_gh1[Hn + i];
            float gin = G[2*Hn + i] + s_gi[32 + tid] + b_ih1[2*Hn + i];
            float rg = 1.f/(1.f + expf(-gir));
            float zg = 1.f/(1.f + expf(-giz));
            float nn = tanhf(gin + rg * g_gh1[2*Hn + i]);
            float hn = (1.f - zg)*nn + zg*g_h1[i];
            g_h1[i] = hn;
            g_o1[i] = (hn >= 0.f) ? hn : 0.01f*hn;
        }
        gsync(ep);

        // ---- Phase E: gi2 (job pairs) + GRU2 combine + q(t+1) column-accumulation ----
        for (int i = tid; i < Hn; i += NT) s_x[i] = g_o1[i];   // ctx persists at s_x[1024..3072)
        __syncthreads();
        {
            int npair = (3*ng + 1) >> 1;
            for (int jp = wid; jp < npair; jp += 16) {
                int itA = 2*jp, itB = 2*jp + 1;
                int vB = (itB < 3*ng);
                int gA = itA % 3, iA = itA / 3;
                int gB = vB ? (itB % 3) : gA, iB = vB ? (itB / 3) : iA;
                const __half* rA = hWih2 + (size_t)(gA*Hn + i0 + iA)*(Hn+Cn);
                const __half* rB = hWih2 + (size_t)(gB*Hn + i0 + iB)*(Hn+Cn);
                float oA, oB;
                dotb2<12>(rA, rB, s_x, lane, oA, oB);
                if (!lane) {
                    s_gi[gA*16 + iA] = oA;
                    if (vB) s_gi[gB*16 + iB] = oB;
                }
            }
        }
        __syncthreads();
        if (tid < ng) {
            int i = i0 + tid;
            float gir = s_gi[tid]      + b_ih2[i]        + g_gh2[i];
            float giz = s_gi[16 + tid] + b_ih2[Hn + i]   + g_gh2[Hn + i];
            float gin = s_gi[32 + tid] + b_ih2[2*Hn + i];
            float rg = 1.f/(1.f + expf(-gir));
            float zg = 1.f/(1.f + expf(-giz));
            float nn = tanhf(gin + rg * g_gh2[2*Hn + i]);
            float hn = (1.f - zg)*nn + zg*g_h2[i];
            g_h2[i] = hn;
            g_o2[i] = (hn >= 0.f) ? hn : 0.01f*hn;
            s_h2n[tid] = hn;
        }
        __syncthreads();
        if (ng > 0 && t + 1 < Tn) {
            float* qn = g_q2[(t+1) & 1];
            const __half* wt = hWqT + (size_t)i0*Hn;
            for (int j2 = tid; j2 < Hn; j2 += NT) {
                float acc = 0.f;
#pragma unroll
                for (int c = 0; c < 7; c++)
                    if (c < ng) acc += s_h2n[c] * __half2float(wt[(size_t)c*Hn + j2]);
                atomicAdd(&qn[j2], acc);
            }
        }
        gsync(ep);
    }

    // ======================= EPILOGUE: out[127], pre[127], h1f, h2f =======================
    for (int i = tid; i < Hn; i += NT) s_x[i] = g_o2[i];
    __syncthreads();
    for (int r = gw; r < 1536; r += nwg) {
        if (r < 512) {
            float s = dotb<4>(hWout + (size_t)r*Hn, s_x, lane);
            if (!lane) out[(size_t)127*En + r] = s + b_out[r];
        } else {
            int rr = r - 512;
            float s = dotb<4>(hWpre + (size_t)rr*(Hn+Cn), s_x, lane);
            if (!lane) {
                float v = s + g_preacc[rr] + b_pre[rr];
                out[OFF_PRE + (size_t)127*Hn + rr] = (v >= 0.f) ? v : 0.01f*v;
            }
        }
    }
    for (int i = gth; i < Hn; i += gstr) {
        out[OFF_H1F + i] = g_h1[i];
        out[OFF_H2F + i] = g_h2[i];
    }
}

extern "C" void kernel_launch(void* const* d_in, const int* in_sizes, int n_in,
                              void* d_out, int out_size) {
    (void)in_sizes; (void)n_in; (void)out_size;
    const int*   inputs = (const int*)  d_in[0];
    const float* h1     = (const float*)d_in[1];
    const float* h2     = (const float*)d_in[2];
    const float* pk     = (const float*)d_in[3];
    const float* enc    = (const float*)d_in[4];
    const float* embeds = (const float*)d_in[5];
    const float* Wq     = (const float*)d_in[6];
    const float* v_att  = (const float*)d_in[7];
    const float* W_ih1  = (const float*)d_in[8];
    const float* W_hh1  = (const float*)d_in[9];
    const float* b_ih1  = (const float*)d_in[10];
    const float* b_hh1  = (const float*)d_in[11];
    const float* W_ih2  = (const float*)d_in[12];
    const float* W_hh2  = (const float*)d_in[13];
    const float* b_ih2  = (const float*)d_in[14];
    const float* b_hh2  = (const float*)d_in[15];
    const float* W_pre  = (const float*)d_in[16];
    const float* b_pre  = (const float*)d_in[17];
    const float* W_out  = (const float*)d_in[18];
    const float* b_out  = (const float*)d_in[19];
    float* out = (float*)d_out;

    int dev = 0, nsm = 148;
    cudaGetDevice(&dev);
    cudaDeviceGetAttribute(&nsm, cudaDevAttrMultiProcessorCount, dev);

    init_kernel<<<2, 1024>>>(h1, h2);
    decoder_persistent<<<nsm, NT>>>(inputs, pk, enc, embeds, Wq, v_att,
                                    W_ih1, W_hh1, b_ih1, b_hh1,
                                    W_ih2, W_hh2, b_ih2, b_hh2,
                                    W_pre, b_pre, W_out, b_out, out);
}